// round 11
// baseline (speedup 1.0000x reference)
#include <cuda_runtime.h>
#include <cuda_pipeline_primitives.h>
#include <cstdint>

// Divergence of (average(M) * gradient(mu)) with periodic boundaries.
// Shapes: (B=16, C=1, H=1024, W=1024) fp32.
// out[p] = sum_ax [ v_ax(p) - v_ax(p - e_ax) ],  v_ax(p) = 0.5*(M[p+e]+M[p])*(mu[p+e]-mu[p])
//
// Two-phase block: 8 rows as two 4-row strips.
//   Prologue: 12 cp.async stage strip-2 rows (h+3..h+8) into smem.
//   Phase 1 : strip-1 rows (h-1..h+4) via 12 direct float4 register loads,
//             shuffle halos, compute rows h..h+3.  (overlaps the cp.async)
//   Phase 2 : after wait+sync, compute rows h+4..h+7 from smem; halos are
//             wrap-indexed smem reads. Memory latency hidden by phase 1.

#define H_DIM 1024
#define W_DIM 1024
#define N_IMG 16

__device__ __forceinline__ float4 row_result(
    const float4 m, const float4 u,
    float mL, float uL, float mR, float uR,
    const float4 mup, const float4 uup,
    const float4 mdn, const float4 udn)
{
    // W-direction forward fluxes (backward flux of elem e == forward of e-1)
    float vm = 0.5f * (m.x + mL)  * (u.x - uL);
    float v0 = 0.5f * (m.y + m.x) * (u.y - u.x);
    float v1 = 0.5f * (m.z + m.y) * (u.z - u.y);
    float v2 = 0.5f * (m.w + m.z) * (u.w - u.z);
    float v3 = 0.5f * (mR  + m.w) * (uR  - u.w);

    float4 r;
    r.x = (v0 - vm) + 0.5f * (mdn.x + m.x) * (udn.x - u.x) - 0.5f * (m.x + mup.x) * (u.x - uup.x);
    r.y = (v1 - v0) + 0.5f * (mdn.y + m.y) * (udn.y - u.y) - 0.5f * (m.y + mup.y) * (u.y - uup.y);
    r.z = (v2 - v1) + 0.5f * (mdn.z + m.z) * (udn.z - u.z) - 0.5f * (m.z + mup.z) * (u.z - uup.z);
    r.w = (v3 - v2) + 0.5f * (mdn.w + m.w) * (udn.w - u.w) - 0.5f * (m.w + mup.w) * (u.w - uup.w);
    return r;
}

__global__ __launch_bounds__(256, 3) void div_grad_kernel(
    const float* __restrict__ M,
    const float* __restrict__ mu,
    float* __restrict__ out)
{
    __shared__ float sM[6][W_DIM];   // 24 KB
    __shared__ float sU[6][W_DIM];   // 24 KB

    const int t    = threadIdx.x;        // 0..255 : float4 column
    const int lane = t & 31;
    const int blk  = blockIdx.x & 127;   // 128 8-row blocks per image
    const int img  = blockIdx.x >> 7;

    const int h0 = blk << 3;             // 0..1016
    const size_t base = (size_t)img << 20;
    const float* Mi = M  + base;
    const float* Ui = mu + base;
    float* Oi = out + base;

    const int wb = t << 2;
    const int wl = (wb - 1) & (W_DIM - 1);
    const int wr = (wb + 4) & (W_DIM - 1);

    // Strip-2 rows: h0+3 .. h0+8 (wrap only possible at the top end)
    // Strip-1 rows: h0-1 .. h0+4 (wrap only at p1[0])
    int p2[6], p1[6];
    #pragma unroll
    for (int i = 0; i < 6; ++i) p2[i] = (h0 + 3 + i) & (H_DIM - 1);
    p1[0] = (h0 - 1) & (H_DIM - 1);
    #pragma unroll
    for (int i = 1; i < 6; ++i) p1[i] = h0 + i - 1;

    // ---- Prologue: stage strip 2 via cp.async (12 register-free requests) --
    #pragma unroll
    for (int i = 0; i < 6; ++i) {
        __pipeline_memcpy_async(&sM[i][wb], Mi + ((size_t)p2[i] << 10) + wb, 16);
        __pipeline_memcpy_async(&sU[i][wb], Ui + ((size_t)p2[i] << 10) + wb, 16);
    }
    __pipeline_commit();

    // ---- Phase 1: strip 1, register-resident (R4 path) ---------------------
    // Boundary-lane halo scalars first (inside the burst window)
    float bM[4], bU[4];
    if (lane == 0) {
        #pragma unroll
        for (int r = 0; r < 4; ++r) {
            bM[r] = Mi[((size_t)p1[r + 1] << 10) + wl];
            bU[r] = Ui[((size_t)p1[r + 1] << 10) + wl];
        }
    } else if (lane == 31) {
        #pragma unroll
        for (int r = 0; r < 4; ++r) {
            bM[r] = Mi[((size_t)p1[r + 1] << 10) + wr];
            bU[r] = Ui[((size_t)p1[r + 1] << 10) + wr];
        }
    } else {
        #pragma unroll
        for (int r = 0; r < 4; ++r) { bM[r] = 0.f; bU[r] = 0.f; }
    }

    float4 m[6], u[6];
    #pragma unroll
    for (int i = 0; i < 6; ++i)
        m[i] = *reinterpret_cast<const float4*>(Mi + ((size_t)p1[i] << 10) + wb);
    #pragma unroll
    for (int i = 0; i < 6; ++i)
        u[i] = *reinterpret_cast<const float4*>(Ui + ((size_t)p1[i] << 10) + wb);

    const unsigned FULL = 0xffffffffu;
    float lM[4], rM[4], lU[4], rU[4];
    #pragma unroll
    for (int r = 0; r < 4; ++r) {
        lM[r] = __shfl_up_sync(FULL, m[r + 1].w, 1);
        lU[r] = __shfl_up_sync(FULL, u[r + 1].w, 1);
        rM[r] = __shfl_down_sync(FULL, m[r + 1].x, 1);
        rU[r] = __shfl_down_sync(FULL, u[r + 1].x, 1);
    }
    if (lane == 0) {
        #pragma unroll
        for (int r = 0; r < 4; ++r) { lM[r] = bM[r]; lU[r] = bU[r]; }
    } else if (lane == 31) {
        #pragma unroll
        for (int r = 0; r < 4; ++r) { rM[r] = bM[r]; rU[r] = bU[r]; }
    }

    // Wait for the staged copies BEFORE the phase-1 stores; the stores and
    // the remaining FMA chain provide the overlap for any residual latency.
    __pipeline_wait_prior(0);

    #pragma unroll
    for (int r = 0; r < 4; ++r) {
        float4 res = row_result(m[r + 1], u[r + 1],
                                lM[r], lU[r], rM[r], rU[r],
                                m[r], u[r], m[r + 2], u[r + 2]);
        *reinterpret_cast<float4*>(Oi + ((size_t)(h0 + r) << 10) + wb) = res;
    }

    __syncthreads();

    // ---- Phase 2: strip 2 from smem (latency hidden by phase 1) -----------
    #pragma unroll
    for (int r = 0; r < 4; ++r) {
        const int c = r + 1;
        const float4 mc  = *reinterpret_cast<const float4*>(&sM[c][wb]);
        const float4 uc  = *reinterpret_cast<const float4*>(&sU[c][wb]);
        const float4 mup = *reinterpret_cast<const float4*>(&sM[c - 1][wb]);
        const float4 uup = *reinterpret_cast<const float4*>(&sU[c - 1][wb]);
        const float4 mdn = *reinterpret_cast<const float4*>(&sM[c + 1][wb]);
        const float4 udn = *reinterpret_cast<const float4*>(&sU[c + 1][wb]);
        const float mL = sM[c][wl], uL = sU[c][wl];
        const float mR = sM[c][wr], uR = sU[c][wr];

        float4 res = row_result(mc, uc, mL, uL, mR, uR, mup, uup, mdn, udn);
        *reinterpret_cast<float4*>(Oi + ((size_t)(h0 + 4 + r) << 10) + wb) = res;
    }
}

extern "C" void kernel_launch(void* const* d_in, const int* in_sizes, int n_in,
                              void* d_out, int out_size)
{
    const float* M  = (const float*)d_in[0];
    const float* mu = (const float*)d_in[1];
    float* out = (float*)d_out;

    const int grid = N_IMG * (H_DIM / 8);  // 2048 blocks, 8 rows each
    div_grad_kernel<<<grid, 256>>>(M, mu, out);
}

// round 12
// speedup vs baseline: 1.1645x; 1.1645x over previous
#include <cuda_runtime.h>
#include <cstdint>

// Divergence of (average(M) * gradient(mu)) with periodic boundaries.
// Shapes: (B=16, C=1, H=1024, W=1024) fp32.
// out[p] = sum_ax [ v_ax(p) - v_ax(p - e_ax) ],  v_ax(p) = 0.5*(M[p+e]+M[p])*(mu[p+e]-mu[p])
//
// Register-burst kernel (R4 lineage), slimmed to 64 regs for 4 CTAs/SM.
// Each thread: one float4 column x 4-row strip; 12 independent float4 loads
// (rows h0-1..h0+4 of M and mu). For interior strips the 6 rows are
// contiguous, so loads use ONE base pointer per array + immediate offsets
// (minimal address registers). Halos (shuffle + boundary-lane L1-hit scalar)
// are resolved per-row inside the compute loop so they never inflate peak
// register pressure during the burst.

#define H_DIM 1024
#define W_DIM 1024
#define N_IMG 16

__device__ __forceinline__ float4 row_result(
    const float4 m, const float4 u,
    float mL, float uL, float mR, float uR,
    const float4 mup, const float4 uup,
    const float4 mdn, const float4 udn)
{
    // W-direction forward fluxes (backward flux of elem e == forward of e-1)
    float vm = 0.5f * (m.x + mL)  * (u.x - uL);
    float v0 = 0.5f * (m.y + m.x) * (u.y - u.x);
    float v1 = 0.5f * (m.z + m.y) * (u.z - u.y);
    float v2 = 0.5f * (m.w + m.z) * (u.w - u.z);
    float v3 = 0.5f * (mR  + m.w) * (uR  - u.w);

    float4 r;
    r.x = (v0 - vm) + 0.5f * (mdn.x + m.x) * (udn.x - u.x) - 0.5f * (m.x + mup.x) * (u.x - uup.x);
    r.y = (v1 - v0) + 0.5f * (mdn.y + m.y) * (udn.y - u.y) - 0.5f * (m.y + mup.y) * (u.y - uup.y);
    r.z = (v2 - v1) + 0.5f * (mdn.z + m.z) * (udn.z - u.z) - 0.5f * (m.z + mup.z) * (u.z - uup.z);
    r.w = (v3 - v2) + 0.5f * (mdn.w + m.w) * (udn.w - u.w) - 0.5f * (m.w + mup.w) * (u.w - uup.w);
    return r;
}

__global__ __launch_bounds__(256, 4) void div_grad_kernel(
    const float* __restrict__ M,
    const float* __restrict__ mu,
    float* __restrict__ out)
{
    const int t     = threadIdx.x;         // 0..255 : float4 column
    const int lane  = t & 31;
    const int strip = blockIdx.x & 255;    // 256 strips of 4 rows per image
    const int img   = blockIdx.x >> 8;

    const int h0 = strip << 2;             // 0..1020
    const size_t base = (size_t)img << 20;
    const float* Mi = M  + base;
    const float* Ui = mu + base;
    const int wb = t << 2;

    float4 m[6], u[6];

    if (h0 != 0 && h0 != (H_DIM - 4)) {
        // Fast path (254/256 strips): rows h0-1..h0+4 contiguous.
        // One base pointer per array; offsets fold into LDG immediates.
        const float* Mb = Mi + (((size_t)(h0 - 1)) << 10) + wb;
        const float* Ub = Ui + (((size_t)(h0 - 1)) << 10) + wb;
        #pragma unroll
        for (int i = 0; i < 6; ++i)
            m[i] = *reinterpret_cast<const float4*>(Mb + (i << 10));
        #pragma unroll
        for (int i = 0; i < 6; ++i)
            u[i] = *reinterpret_cast<const float4*>(Ub + (i << 10));
    } else {
        // Slow path (2 strips): wrap-aware row indices.
        #pragma unroll
        for (int i = 0; i < 6; ++i) {
            const int hr = (h0 - 1 + i) & (H_DIM - 1);
            m[i] = *reinterpret_cast<const float4*>(Mi + ((size_t)hr << 10) + wb);
            u[i] = *reinterpret_cast<const float4*>(Ui + ((size_t)hr << 10) + wb);
        }
    }

    const int wl = (wb - 1) & (W_DIM - 1);
    const int wr = (wb + 4) & (W_DIM - 1);
    const unsigned FULL = 0xffffffffu;
    float* Oi = out + base;

    #pragma unroll
    for (int r = 0; r < 4; ++r) {
        const int c = r + 1;

        // Horizontal halos: shuffle of in-register neighbors; edge lanes take
        // an L1-hit scalar (the line was loaded by the adjacent thread).
        float lM = __shfl_up_sync(FULL, m[c].w, 1);
        float lU = __shfl_up_sync(FULL, u[c].w, 1);
        float rM = __shfl_down_sync(FULL, m[c].x, 1);
        float rU = __shfl_down_sync(FULL, u[c].x, 1);
        if (lane == 0) {
            const float* Mrow = Mi + ((size_t)(h0 + r) << 10);
            const float* Urow = Ui + ((size_t)(h0 + r) << 10);
            lM = Mrow[wl]; lU = Urow[wl];
        } else if (lane == 31) {
            const float* Mrow = Mi + ((size_t)(h0 + r) << 10);
            const float* Urow = Ui + ((size_t)(h0 + r) << 10);
            rM = Mrow[wr]; rU = Urow[wr];
        }

        float4 res = row_result(m[c], u[c], lM, lU, rM, rU,
                                m[c - 1], u[c - 1], m[c + 1], u[c + 1]);
        *reinterpret_cast<float4*>(Oi + ((size_t)(h0 + r) << 10) + wb) = res;
    }
}

extern "C" void kernel_launch(void* const* d_in, const int* in_sizes, int n_in,
                              void* d_out, int out_size)
{
    const float* M  = (const float*)d_in[0];
    const float* mu = (const float*)d_in[1];
    float* out = (float*)d_out;

    const int grid = N_IMG * (H_DIM / 4);  // 4096 blocks, one 4-row strip each
    div_grad_kernel<<<grid, 256>>>(M, mu, out);
}

// round 13
// speedup vs baseline: 1.2362x; 1.0616x over previous
#include <cuda_runtime.h>
#include <cstdint>

// Divergence of (average(M) * gradient(mu)) with periodic boundaries.
// Shapes: (B=16, C=1, H=1024, W=1024) fp32.
// out[p] = sum_ax [ v_ax(p) - v_ax(p - e_ax) ],  v_ax(p) = 0.5*(M[p+e]+M[p])*(mu[p+e]-mu[p])
//
// Register-burst kernel. Each thread: one float4 column x 4-row strip.
// FRONT BURST (all independent, nothing memory-dependent after it):
//   - 12 float4 loads: rows h0-1..h0+4 of M and mu (base + immediate offsets
//     for interior strips -> minimal address registers)
//   - lane 0/31 only: 8 wrap-aware boundary halo scalars
// Then pure compute: in-loop shuffles (ALU only) + FMA + stores.
// 64-reg budget -> 4 CTAs/SM.

#define H_DIM 1024
#define W_DIM 1024
#define N_IMG 16

__device__ __forceinline__ float4 row_result(
    const float4 m, const float4 u,
    float mL, float uL, float mR, float uR,
    const float4 mup, const float4 uup,
    const float4 mdn, const float4 udn)
{
    // W-direction forward fluxes (backward flux of elem e == forward of e-1)
    float vm = 0.5f * (m.x + mL)  * (u.x - uL);
    float v0 = 0.5f * (m.y + m.x) * (u.y - u.x);
    float v1 = 0.5f * (m.z + m.y) * (u.z - u.y);
    float v2 = 0.5f * (m.w + m.z) * (u.w - u.z);
    float v3 = 0.5f * (mR  + m.w) * (uR  - u.w);

    float4 r;
    r.x = (v0 - vm) + 0.5f * (mdn.x + m.x) * (udn.x - u.x) - 0.5f * (m.x + mup.x) * (u.x - uup.x);
    r.y = (v1 - v0) + 0.5f * (mdn.y + m.y) * (udn.y - u.y) - 0.5f * (m.y + mup.y) * (u.y - uup.y);
    r.z = (v2 - v1) + 0.5f * (mdn.z + m.z) * (udn.z - u.z) - 0.5f * (m.z + mup.z) * (u.z - uup.z);
    r.w = (v3 - v2) + 0.5f * (mdn.w + m.w) * (udn.w - u.w) - 0.5f * (m.w + mup.w) * (u.w - uup.w);
    return r;
}

__global__ __launch_bounds__(256, 4) void div_grad_kernel(
    const float* __restrict__ M,
    const float* __restrict__ mu,
    float* __restrict__ out)
{
    const int t     = threadIdx.x;         // 0..255 : float4 column
    const int lane  = t & 31;
    const int strip = blockIdx.x & 255;    // 256 strips of 4 rows per image
    const int img   = blockIdx.x >> 8;

    const int h0 = strip << 2;             // 0..1020
    const size_t base = (size_t)img << 20;
    const float* Mi = M  + base;
    const float* Ui = mu + base;
    const int wb = t << 2;
    const int wl = (wb - 1) & (W_DIM - 1);
    const int wr = (wb + 4) & (W_DIM - 1);

    float4 m[6], u[6];
    float bM[4], bU[4];

    if (h0 != 0 && h0 != (H_DIM - 4)) {
        // Fast path (254/256 strips): rows h0-1..h0+4 contiguous.
        const float* Mb = Mi + (((size_t)(h0 - 1)) << 10) + wb;
        const float* Ub = Ui + (((size_t)(h0 - 1)) << 10) + wb;
        #pragma unroll
        for (int i = 0; i < 6; ++i)
            m[i] = *reinterpret_cast<const float4*>(Mb + (i << 10));
        #pragma unroll
        for (int i = 0; i < 6; ++i)
            u[i] = *reinterpret_cast<const float4*>(Ub + (i << 10));

        // Boundary halo scalars, still in the burst window (independent).
        const float* Mrow0 = Mi + ((size_t)h0 << 10);
        const float* Urow0 = Ui + ((size_t)h0 << 10);
        if (lane == 0) {
            #pragma unroll
            for (int r = 0; r < 4; ++r) {
                bM[r] = Mrow0[(r << 10) + wl];
                bU[r] = Urow0[(r << 10) + wl];
            }
        } else if (lane == 31) {
            #pragma unroll
            for (int r = 0; r < 4; ++r) {
                bM[r] = Mrow0[(r << 10) + wr];
                bU[r] = Urow0[(r << 10) + wr];
            }
        } else {
            #pragma unroll
            for (int r = 0; r < 4; ++r) { bM[r] = 0.f; bU[r] = 0.f; }
        }
    } else {
        // Slow path (2 strips): wrap-aware row indices.
        #pragma unroll
        for (int i = 0; i < 6; ++i) {
            const int hr = (h0 - 1 + i) & (H_DIM - 1);
            m[i] = *reinterpret_cast<const float4*>(Mi + ((size_t)hr << 10) + wb);
            u[i] = *reinterpret_cast<const float4*>(Ui + ((size_t)hr << 10) + wb);
        }
        const int wx = (lane == 0) ? wl : wr;
        if (lane == 0 || lane == 31) {
            #pragma unroll
            for (int r = 0; r < 4; ++r) {
                bM[r] = Mi[((size_t)(h0 + r) << 10) + wx];
                bU[r] = Ui[((size_t)(h0 + r) << 10) + wx];
            }
        } else {
            #pragma unroll
            for (int r = 0; r < 4; ++r) { bM[r] = 0.f; bU[r] = 0.f; }
        }
    }

    const unsigned FULL = 0xffffffffu;
    float* Oi = out + base;

    #pragma unroll
    for (int r = 0; r < 4; ++r) {
        const int c = r + 1;

        // Horizontal halos: shuffles (ALU path); edge lanes use prefetched scalars.
        float lM = __shfl_up_sync(FULL, m[c].w, 1);
        float lU = __shfl_up_sync(FULL, u[c].w, 1);
        float rM = __shfl_down_sync(FULL, m[c].x, 1);
        float rU = __shfl_down_sync(FULL, u[c].x, 1);
        if (lane == 0)       { lM = bM[r]; lU = bU[r]; }
        else if (lane == 31) { rM = bM[r]; rU = bU[r]; }

        float4 res = row_result(m[c], u[c], lM, lU, rM, rU,
                                m[c - 1], u[c - 1], m[c + 1], u[c + 1]);
        *reinterpret_cast<float4*>(Oi + ((size_t)(h0 + r) << 10) + wb) = res;
    }
}

extern "C" void kernel_launch(void* const* d_in, const int* in_sizes, int n_in,
                              void* d_out, int out_size)
{
    const float* M  = (const float*)d_in[0];
    const float* mu = (const float*)d_in[1];
    float* out = (float*)d_out;

    const int grid = N_IMG * (H_DIM / 4);  // 4096 blocks, one 4-row strip each
    div_grad_kernel<<<grid, 256>>>(M, mu, out);
}